// round 2
// baseline (speedup 1.0000x reference)
#include <cuda_runtime.h>
#include <math.h>

// ---------------- problem constants (fixed by setup_inputs) ----------------
#define NN 131072      // nodes
#define EE 2097152     // edges
#define BB 128         // graphs
#define NPG 1024       // nodes per graph
#define HH 128         // hidden
#define TT 8           // virtual tokens
#define NHEAD 4
#define HD 32
#define II 256         // mamba intermediate
#define SS 16          // mamba state
#define RR 8           // dt rank
#define KK 4           // conv kernel

// ---------------- device scratch (static; allocation is forbidden) ---------
__device__ float g_x[NN * HH];
__device__ float g_agg[NN * HH];
__device__ float g_g[NN * HH];
__device__ float g_k[NN * HH];
__device__ float g_v[NN * HH];
__device__ float g_q[TT * HH];
__device__ float g_o[BB * TT * HH];
__device__ float g_tok[BB * TT * HH];
__device__ float g_gf[BB * HH];

__device__ int g_deg[NN];
__device__ int g_start[NN];
__device__ int g_cursor[NN];
__device__ int g_eid[EE];
__device__ int g_bsum[NN / 1024];
__device__ int g_bbase[NN / 1024];

// ---------------- CSR build ----------------
__global__ void k_zero_dc() {
    int i = blockIdx.x * 256 + threadIdx.x;
    if (i < NN) { g_deg[i] = 0; g_cursor[i] = 0; }
}

__global__ void k_degree(const int* __restrict__ ei) {
    int e = blockIdx.x * 256 + threadIdx.x;
    if (e < EE) atomicAdd(&g_deg[ei[EE + e]], 1);
}

// inclusive block scan of 1024 elems/block; writes local inclusive into g_start
__global__ void k_scan1() {
    __shared__ int wsum[32];
    int i = blockIdx.x * 1024 + threadIdx.x;
    int lane = threadIdx.x & 31, wid = threadIdx.x >> 5;
    int s = g_deg[i];
    #pragma unroll
    for (int d = 1; d < 32; d <<= 1) {
        int t = __shfl_up_sync(0xffffffffu, s, d);
        if (lane >= d) s += t;
    }
    if (lane == 31) wsum[wid] = s;
    __syncthreads();
    if (wid == 0) {
        int ws = wsum[lane];
        #pragma unroll
        for (int d = 1; d < 32; d <<= 1) {
            int t = __shfl_up_sync(0xffffffffu, ws, d);
            if (lane >= d) ws += t;
        }
        wsum[lane] = ws;
    }
    __syncthreads();
    int incl = s + (wid > 0 ? wsum[wid - 1] : 0);
    g_start[i] = incl;
    if (threadIdx.x == 1023) g_bsum[blockIdx.x] = incl;
}

__global__ void k_scan2() {
    if (threadIdx.x == 0) {
        int run = 0;
        for (int b = 0; b < NN / 1024; b++) { int t = g_bsum[b]; g_bbase[b] = run; run += t; }
    }
}

__global__ void k_scan3() {
    int i = blockIdx.x * 256 + threadIdx.x;
    if (i < NN) g_start[i] = g_start[i] - g_deg[i] + g_bbase[i >> 10];
}

__global__ void k_scatter(const int* __restrict__ ei) {
    int e = blockIdx.x * 256 + threadIdx.x;
    if (e < EE) {
        int d = ei[EE + e];
        int p = atomicAdd(&g_cursor[d], 1);
        g_eid[g_start[d] + p] = ei[e];
    }
}

// ---------------- edge aggregation: agg[n] = x[n] + sum_{src->n} x[src] ----
__global__ void k_aggregate(const float* __restrict__ in) {
    int node = blockIdx.x * 8 + (threadIdx.x >> 5);
    int lane = threadIdx.x & 31;
    int c = lane * 4;
    float4 acc = *(const float4*)&in[(size_t)node * HH + c];
    int s0 = g_start[node];
    int d = g_deg[node];
    for (int e = 0; e < d; e++) {
        int src = g_eid[s0 + e];
        float4 v = __ldg((const float4*)&in[(size_t)src * HH + c]);
        acc.x += v.x; acc.y += v.y; acc.z += v.z; acc.w += v.w;
    }
    *(float4*)&g_agg[(size_t)node * HH + c] = acc;
}

// ---------------- GEMM: out[r, j] = bias[boff+j] + sum_k in[r,k]*W[k*wld+woff+j]
// K = 128, J = 128 fixed. 32 rows/block, 256 threads, 4x4 register tile.
__global__ void k_matmul(const float* __restrict__ in, int in_ld,
                         const float* __restrict__ W, int w_ld, int w_off,
                         const float* __restrict__ bias, int b_off,
                         float* __restrict__ out, int out_ld, int rows) {
    __shared__ float sA[32][128];
    int row0 = blockIdx.x * 32;
    for (int i = threadIdx.x; i < 32 * 128; i += 256) {
        int r = i >> 7, c = i & 127;
        sA[r][c] = (row0 + r < rows) ? in[(size_t)(row0 + r) * in_ld + c] : 0.f;
    }
    __syncthreads();
    int tj = threadIdx.x & 31, tm = threadIdx.x >> 5;
    int j4 = tj * 4;
    float acc[4][4] = {};
    const float* Wp = W + w_off + j4;
    #pragma unroll 4
    for (int k0 = 0; k0 < 128; k0 += 4) {
        float4 a0 = *(const float4*)&sA[tm * 4 + 0][k0];
        float4 a1 = *(const float4*)&sA[tm * 4 + 1][k0];
        float4 a2 = *(const float4*)&sA[tm * 4 + 2][k0];
        float4 a3 = *(const float4*)&sA[tm * 4 + 3][k0];
        float av[4][4] = {{a0.x, a0.y, a0.z, a0.w},
                          {a1.x, a1.y, a1.z, a1.w},
                          {a2.x, a2.y, a2.z, a2.w},
                          {a3.x, a3.y, a3.z, a3.w}};
        #pragma unroll
        for (int kk = 0; kk < 4; kk++) {
            float4 w = __ldg((const float4*)(Wp + (size_t)(k0 + kk) * w_ld));
            #pragma unroll
            for (int m = 0; m < 4; m++) {
                acc[m][0] += av[m][kk] * w.x;
                acc[m][1] += av[m][kk] * w.y;
                acc[m][2] += av[m][kk] * w.z;
                acc[m][3] += av[m][kk] * w.w;
            }
        }
    }
    float4 bv = *(const float4*)&bias[b_off + j4];
    #pragma unroll
    for (int m = 0; m < 4; m++) {
        int r = row0 + tm * 4 + m;
        if (r < rows) {
            float4 o;
            o.x = acc[m][0] + bv.x; o.y = acc[m][1] + bv.y;
            o.z = acc[m][2] + bv.z; o.w = acc[m][3] + bv.w;
            *(float4*)&out[(size_t)r * out_ld + j4] = o;
        }
    }
}

// ---------------- attention: one block per (graph, head) -------------------
__global__ void k_attn() {
    __shared__ float s_q[8][32];
    __shared__ float s_kt[64 * 37];
    __shared__ float s_sc[8][1024];
    int b = blockIdx.x >> 2, h = blockIdx.x & 3;
    int tid = threadIdx.x;
    {
        int t = tid >> 5, d = tid & 31;
        s_q[t][d] = g_q[t * HH + h * 32 + d];
    }
    __syncthreads();
    int t = tid >> 5, g = tid & 31;
    float qr[32];
    #pragma unroll
    for (int d = 0; d < 32; d++) qr[d] = s_q[t][d];
    const float scale = 0.17677669529663689f;  // 1/sqrt(32)

    for (int kk0 = 0; kk0 < 1024; kk0 += 64) {
        __syncthreads();
        for (int i = tid; i < 64 * 32; i += 256) {
            int key = i >> 5, d = i & 31;
            s_kt[key * 37 + d] = g_k[((size_t)(b * 1024 + kk0 + key)) * HH + h * 32 + d];
        }
        __syncthreads();
        #pragma unroll
        for (int kidx = 0; kidx < 2; kidx++) {
            int key = g + kidx * 32;
            float acc = 0.f;
            #pragma unroll
            for (int d = 0; d < 32; d++) acc += s_kt[key * 37 + d] * qr[d];
            s_sc[t][kk0 + key] = acc * scale;
        }
    }
    __syncthreads();
    // softmax over 1024 keys; warp t owns row t
    float m = -1e30f;
    for (int i = g; i < 1024; i += 32) m = fmaxf(m, s_sc[t][i]);
    #pragma unroll
    for (int d = 16; d; d >>= 1) m = fmaxf(m, __shfl_xor_sync(0xffffffffu, m, d));
    float sum = 0.f;
    for (int i = g; i < 1024; i += 32) {
        float e = __expf(s_sc[t][i] - m);
        s_sc[t][i] = e;
        sum += e;
    }
    #pragma unroll
    for (int d = 16; d; d >>= 1) sum += __shfl_xor_sync(0xffffffffu, sum, d);
    float inv = 1.f / sum;
    for (int i = g; i < 1024; i += 32) s_sc[t][i] *= inv;
    __syncthreads();
    // o[t][d] = sum_kk attn * v
    float acc = 0.f;
    const float* vbase = g_v + (size_t)b * 1024 * HH + h * 32 + g;
    #pragma unroll 4
    for (int kk = 0; kk < 1024; kk++)
        acc += s_sc[t][kk] * __ldg(vbase + (size_t)kk * HH);
    g_o[((size_t)b * 8 + t) * HH + h * 32 + g] = acc;
}

// ---------------- mamba: one block per batch element, 256 threads ----------
__global__ void k_mamba(const float* __restrict__ in_w, const float* __restrict__ conv_w,
                        const float* __restrict__ conv_b, const float* __restrict__ x_w,
                        const float* __restrict__ dt_w, const float* __restrict__ dt_b,
                        const float* __restrict__ A_log, const float* __restrict__ Dp,
                        const float* __restrict__ out_w, const float* __restrict__ norm_w,
                        const float* __restrict__ normf_w) {
    __shared__ float s_res[8][128];
    __shared__ float s_h[8][128];
    __shared__ float s_u[8][256];
    __shared__ float s_ssm[8][40];
    __shared__ float s_y[8][256];
    __shared__ float s_o[8][128];
    __shared__ float s_r[8];
    int b = blockIdx.x, tid = threadIdx.x;

    for (int i = tid; i < 8 * 128; i += 256)
        s_res[i >> 7][i & 127] = g_tok[(size_t)b * 1024 + i];
    __syncthreads();
    // rmsnorm(tokens)
    {
        int t = tid >> 5, lane = tid & 31;
        float ss = 0.f;
        for (int c = lane; c < 128; c += 32) { float v = s_res[t][c]; ss += v * v; }
        #pragma unroll
        for (int d = 16; d; d >>= 1) ss += __shfl_xor_sync(0xffffffffu, ss, d);
        float r = rsqrtf(ss / 128.f + 1e-5f);
        for (int c = lane; c < 128; c += 32) s_h[t][c] = s_res[t][c] * r * norm_w[c];
    }
    __syncthreads();

    int i = tid;  // channel 0..255
    float u_r[8] = {}, gate_r[8] = {};
    for (int k = 0; k < 128; k++) {
        float w0 = __ldg(&in_w[k * 512 + i]);
        float w1 = __ldg(&in_w[k * 512 + 256 + i]);
        #pragma unroll
        for (int t = 0; t < 8; t++) {
            float hv = s_h[t][k];
            u_r[t] += hv * w0;
            gate_r[t] += hv * w1;
        }
    }
    // causal depthwise conv (K=4) + silu
    float cw0 = conv_w[i * 4 + 0], cw1 = conv_w[i * 4 + 1];
    float cw2 = conv_w[i * 4 + 2], cw3 = conv_w[i * 4 + 3];
    float cb = conv_b[i];
    float uc[8];
    #pragma unroll
    for (int t = 0; t < 8; t++) {
        float c = cb + cw3 * u_r[t];
        if (t >= 1) c += cw2 * u_r[t - 1];
        if (t >= 2) c += cw1 * u_r[t - 2];
        if (t >= 3) c += cw0 * u_r[t - 3];
        uc[t] = c / (1.f + expf(-c));
        s_u[t][i] = uc[t];
    }
    __syncthreads();
    // ssm projection: [8,256] @ [256,40]
    for (int idx = tid; idx < 8 * 40; idx += 256) {
        int t = idx / 40, j = idx % 40;
        float a = 0.f;
        for (int k = 0; k < 256; k++) a += s_u[t][k] * __ldg(&x_w[k * 40 + j]);
        s_ssm[t][j] = a;
    }
    __syncthreads();
    // dt = softplus(dtr @ dt_w + dt_b)
    float dtv[8];
    {
        float acc[8] = {};
        for (int r = 0; r < 8; r++) {
            float w = __ldg(&dt_w[r * 256 + i]);
            #pragma unroll
            for (int t = 0; t < 8; t++) acc[t] += s_ssm[t][r] * w;
        }
        float db = dt_b[i];
        #pragma unroll
        for (int t = 0; t < 8; t++) {
            float a = acc[t] + db;
            dtv[t] = (a > 20.f) ? a : log1pf(expf(a));
        }
    }
    // selective scan over T=8
    float Ar[16];
    #pragma unroll
    for (int s = 0; s < 16; s++) Ar[s] = -expf(A_log[i * 16 + s]);
    float Dv = Dp[i];
    float hst[16] = {};
    #pragma unroll
    for (int t = 0; t < 8; t++) {
        float dtt = dtv[t], ut = uc[t];
        float y = 0.f;
        #pragma unroll
        for (int s = 0; s < 16; s++) {
            float dA = expf(dtt * Ar[s]);
            hst[s] = dA * hst[s] + dtt * s_ssm[t][8 + s] * ut;
            y += hst[s] * s_ssm[t][24 + s];
        }
        y += ut * Dv;
        float gt = gate_r[t];
        y *= gt / (1.f + expf(-gt));
        s_y[t][i] = y;
    }
    __syncthreads();
    // out proj + residual
    for (int idx = tid; idx < 8 * 128; idx += 256) {
        int t = idx >> 7, j = idx & 127;
        float a = 0.f;
        for (int k = 0; k < 256; k++) a += s_y[t][k] * __ldg(&out_w[k * 128 + j]);
        s_o[t][j] = s_res[t][j] + a;
    }
    __syncthreads();
    // final rmsnorm + mean over T
    {
        int t = tid >> 5, lane = tid & 31;
        float ss = 0.f;
        for (int c = lane; c < 128; c += 32) { float v = s_o[t][c]; ss += v * v; }
        #pragma unroll
        for (int d = 16; d; d >>= 1) ss += __shfl_xor_sync(0xffffffffu, ss, d);
        if (lane == 0) s_r[t] = rsqrtf(ss / 128.f + 1e-5f);
    }
    __syncthreads();
    if (tid < 128) {
        float a = 0.f;
        #pragma unroll
        for (int t = 0; t < 8; t++) a += s_o[t][tid] * s_r[t];
        g_gf[b * 128 + tid] = a * normf_w[tid] * 0.125f;
    }
}

// ---------------- x = g + gf[batch] ----------------------------------------
__global__ void k_update() {
    int idx = blockIdx.x * 256 + threadIdx.x;  // covers N*H
    g_x[idx] = g_g[idx] + g_gf[((idx >> 17) << 7) | (idx & 127)];
}

// ---------------- final per-graph reduction --------------------------------
__global__ void k_out(float* __restrict__ out) {
    int b = blockIdx.x, j = threadIdx.x;
    float a = 0.f;
    const float* p = g_g + (size_t)b * NPG * HH + j;
    #pragma unroll 8
    for (int n = 0; n < NPG; n++) a += p[(size_t)n * HH];
    out[b * HH + j] = a;
}

// ---------------- host launch ----------------------------------------------
extern "C" void kernel_launch(void* const* d_in, const int* in_sizes, int n_in,
                              void* d_out, int out_size) {
    // index shift if the scalar ints (num_graphs, nodes_per_graph) are absent
    int off = (n_in >= 27) ? 0 : -2;
    auto P = [&](int i) -> const void* { return (i < 3) ? d_in[i] : d_in[i + off]; };

    const float* x_in   = (const float*)P(0);
    const int*   ei     = (const int*)P(1);
    const float* w_in   = (const float*)P(5);
    const float* b_in   = (const float*)P(6);
    const float* gin_w  = (const float*)P(7);
    const float* gin_b  = (const float*)P(8);
    const float* vt     = (const float*)P(9);
    const float* qkv_w  = (const float*)P(10);
    const float* qkv_b  = (const float*)P(11);
    const float* ao_w   = (const float*)P(12);
    const float* ao_b   = (const float*)P(13);
    const float* m_in_w   = (const float*)P(14);
    const float* m_conv_w = (const float*)P(15);
    const float* m_conv_b = (const float*)P(16);
    const float* m_x_w    = (const float*)P(17);
    const float* m_dt_w   = (const float*)P(18);
    const float* m_dt_b   = (const float*)P(19);
    const float* m_A_log  = (const float*)P(20);
    const float* m_D      = (const float*)P(21);
    const float* m_out_w  = (const float*)P(22);
    const float* m_norm_w = (const float*)P(23);
    const float* m_normf_w= (const float*)P(24);
    const float* w_out  = (const float*)P(25);
    const float* b_out  = (const float*)P(26);

    float *p_x, *p_agg, *p_g, *p_k, *p_v, *p_q, *p_o, *p_tok;
    cudaGetSymbolAddress((void**)&p_x, g_x);
    cudaGetSymbolAddress((void**)&p_agg, g_agg);
    cudaGetSymbolAddress((void**)&p_g, g_g);
    cudaGetSymbolAddress((void**)&p_k, g_k);
    cudaGetSymbolAddress((void**)&p_v, g_v);
    cudaGetSymbolAddress((void**)&p_q, g_q);
    cudaGetSymbolAddress((void**)&p_o, g_o);
    cudaGetSymbolAddress((void**)&p_tok, g_tok);

    // --- CSR build ---
    k_zero_dc<<<(NN + 255) / 256, 256>>>();
    k_degree<<<(EE + 255) / 256, 256>>>(ei);
    k_scan1<<<NN / 1024, 1024>>>();
    k_scan2<<<1, 32>>>();
    k_scan3<<<(NN + 255) / 256, 256>>>();
    k_scatter<<<(EE + 255) / 256, 256>>>(ei);

    // --- GIN input layer: x = gin(x_in, w_in, b_in) ---
    k_aggregate<<<NN / 8, 256>>>(x_in);
    k_matmul<<<NN / 32, 256>>>(p_agg, HH, w_in, HH, 0, b_in, 0, p_x, HH, NN);

    // --- two (GIN + attn-pool + mamba) blocks ---
    for (int l = 0; l < 2; l++) {
        // g = gin(x)
        k_aggregate<<<NN / 8, 256>>>(p_x);
        k_matmul<<<NN / 32, 256>>>(p_agg, HH, gin_w + l * HH * HH, HH, 0,
                                   gin_b + l * HH, 0, p_g, HH, NN);
        // K, V projections from x
        k_matmul<<<NN / 32, 256>>>(p_x, HH, qkv_w + l * HH * 3 * HH, 3 * HH, HH,
                                   qkv_b + l * 3 * HH, HH, p_k, HH, NN);
        k_matmul<<<NN / 32, 256>>>(p_x, HH, qkv_w + l * HH * 3 * HH, 3 * HH, 2 * HH,
                                   qkv_b + l * 3 * HH, 2 * HH, p_v, HH, NN);
        // q = vt @ Wq + bq  (8 rows)
        k_matmul<<<1, 256>>>(vt + l * TT * HH, HH, qkv_w + l * HH * 3 * HH, 3 * HH, 0,
                             qkv_b + l * 3 * HH, 0, p_q, HH, TT);
        // attention pool
        k_attn<<<BB * NHEAD, 256>>>();
        // tokens = o @ ao_w + ao_b  (B*T rows)
        k_matmul<<<(BB * TT) / 32, 256>>>(p_o, HH, ao_w + l * HH * HH, HH, 0,
                                          ao_b + l * HH, 0, p_tok, HH, BB * TT);
        // mamba -> g_gf
        k_mamba<<<BB, 256>>>(m_in_w, m_conv_w, m_conv_b, m_x_w, m_dt_w, m_dt_b,
                             m_A_log, m_D, m_out_w, m_norm_w, m_normf_w);
        // x = g + gf[batch]
        k_update<<<(NN * HH) / 256, 256>>>();
    }

    // --- output GIN + per-graph sum ---
    k_aggregate<<<NN / 8, 256>>>(p_x);
    k_matmul<<<NN / 32, 256>>>(p_agg, HH, w_out, HH, 0, b_out, 0, p_g, HH, NN);
    k_out<<<BB, HH>>>((float*)d_out);
}

// round 3
// speedup vs baseline: 1.4525x; 1.4525x over previous
#include <cuda_runtime.h>
#include <math.h>

// ---------------- problem constants (fixed by setup_inputs) ----------------
#define NN 131072
#define EE 2097152
#define BB 128
#define NPG 1024
#define HH 128
#define TT 8

// ---------------- device scratch ----------------
__device__ float g_x[NN * HH];
__device__ float g_agg[NN * HH];
__device__ float g_k[NN * HH];
__device__ float g_v[NN * HH];
__device__ float g_q[TT * HH];
__device__ float g_o[BB * TT * HH];
__device__ float g_tok[BB * TT * HH];
__device__ float g_gf[BB * HH];
__device__ float g_gs[BB * HH];

__device__ int g_deg[NN];
__device__ int g_start[NN];
__device__ int g_cursor[NN];
__device__ int g_eid[EE];
__device__ int g_bsum[NN / 1024];
__device__ int g_bbase[NN / 1024];

// ---------------- CSR build ----------------
__global__ void k_zero_dc() {
    int i = blockIdx.x * 256 + threadIdx.x;
    if (i < NN) { g_deg[i] = 0; g_cursor[i] = 0; }
}

__global__ void k_degree(const int* __restrict__ ei) {
    int e = blockIdx.x * 256 + threadIdx.x;
    if (e < EE) atomicAdd(&g_deg[ei[EE + e]], 1);
}

__global__ void k_scan1() {
    __shared__ int wsum[32];
    int i = blockIdx.x * 1024 + threadIdx.x;
    int lane = threadIdx.x & 31, wid = threadIdx.x >> 5;
    int s = g_deg[i];
    #pragma unroll
    for (int d = 1; d < 32; d <<= 1) {
        int t = __shfl_up_sync(0xffffffffu, s, d);
        if (lane >= d) s += t;
    }
    if (lane == 31) wsum[wid] = s;
    __syncthreads();
    if (wid == 0) {
        int ws = wsum[lane];
        #pragma unroll
        for (int d = 1; d < 32; d <<= 1) {
            int t = __shfl_up_sync(0xffffffffu, ws, d);
            if (lane >= d) ws += t;
        }
        wsum[lane] = ws;
    }
    __syncthreads();
    int incl = s + (wid > 0 ? wsum[wid - 1] : 0);
    g_start[i] = incl;
    if (threadIdx.x == 1023) g_bsum[blockIdx.x] = incl;
}

__global__ void k_scan2() {
    if (threadIdx.x == 0) {
        int run = 0;
        for (int b = 0; b < NN / 1024; b++) { int t = g_bsum[b]; g_bbase[b] = run; run += t; }
    }
}

__global__ void k_scan3() {
    int i = blockIdx.x * 256 + threadIdx.x;
    if (i < NN) g_start[i] = g_start[i] - g_deg[i] + g_bbase[i >> 10];
}

__global__ void k_scatter(const int* __restrict__ ei) {
    int e = blockIdx.x * 256 + threadIdx.x;
    if (e < EE) {
        int d = ei[EE + e];
        int p = atomicAdd(&g_cursor[d], 1);
        g_eid[g_start[d] + p] = ei[e];
    }
}

// ---------------- edge aggregation: agg[n] = x[n] + sum_{src->n} x[src] ----
__global__ void k_aggregate(const float* __restrict__ in) {
    int node = blockIdx.x * 8 + (threadIdx.x >> 5);
    int lane = threadIdx.x & 31;
    int c = lane * 4;
    float4 acc = *(const float4*)&in[(size_t)node * HH + c];
    int s0 = g_start[node];
    int d = g_deg[node];
    for (int e = 0; e < d; e++) {
        int src = g_eid[s0 + e];
        float4 v = __ldg((const float4*)&in[(size_t)src * HH + c]);
        acc.x += v.x; acc.y += v.y; acc.z += v.z; acc.w += v.w;
    }
    *(float4*)&g_agg[(size_t)node * HH + c] = acc;
}

// ---------------- big SGEMM: rows x 128 @ 128 x 128 -------------------------
// block tile 128x128, 256 threads, 8x8 per thread split as {ty*4, 64+ty*4} x
// {tx*4, 64+tx*4} for conflict-free LDS.128. Double-buffered 8-wide K chunks.
// out[r][j] = bias[b_off+j] + sum_k A[r*128+k] * W[k*w_ld + w_off + j]
//             (+ addv[(r>>10)*128 + j] if addv != nullptr)
__global__ __launch_bounds__(256, 2)
void k_gemm128(const float* __restrict__ A,
               const float* __restrict__ W, int w_ld, int w_off,
               const float* __restrict__ bias, int b_off,
               float* __restrict__ out,
               const float* __restrict__ addv) {
    __shared__ float sA[2][8][132];
    __shared__ float sB[2][8][128];
    int tid = threadIdx.x;
    size_t row0 = (size_t)blockIdx.x * 128;

    // loader indices
    int la_r = tid >> 1;                 // 0..127
    int la_k = (tid & 1) * 4;            // 0 or 4
    int lb_k = tid >> 5;                 // 0..7
    int lb_j = (tid & 31) * 4;
    const float* Ap = A + (row0 + la_r) * 128 + la_k;
    const float* Wp = W + w_off + lb_j + (size_t)lb_k * w_ld;

    float4 ra = *(const float4*)Ap;
    float4 rb = __ldg((const float4*)Wp);
    sA[0][la_k + 0][la_r] = ra.x; sA[0][la_k + 1][la_r] = ra.y;
    sA[0][la_k + 2][la_r] = ra.z; sA[0][la_k + 3][la_r] = ra.w;
    *(float4*)&sB[0][lb_k][lb_j] = rb;
    __syncthreads();

    int ty = tid >> 4, tx = tid & 15;
    int r4 = ty * 4, c4 = tx * 4;
    float acc[8][8] = {};

    #pragma unroll 1
    for (int c = 0; c < 16; c++) {
        int buf = c & 1;
        if (c < 15) {
            ra = *(const float4*)(Ap + (c + 1) * 8);
            rb = __ldg((const float4*)(Wp + (size_t)(c + 1) * 8 * w_ld));
        }
        #pragma unroll
        for (int k = 0; k < 8; k++) {
            float4 a0 = *(const float4*)&sA[buf][k][r4];
            float4 a1 = *(const float4*)&sA[buf][k][64 + r4];
            float4 b0 = *(const float4*)&sB[buf][k][c4];
            float4 b1 = *(const float4*)&sB[buf][k][64 + c4];
            float av[8] = {a0.x, a0.y, a0.z, a0.w, a1.x, a1.y, a1.z, a1.w};
            float bv[8] = {b0.x, b0.y, b0.z, b0.w, b1.x, b1.y, b1.z, b1.w};
            #pragma unroll
            for (int i = 0; i < 8; i++)
                #pragma unroll
                for (int j = 0; j < 8; j++)
                    acc[i][j] += av[i] * bv[j];
        }
        if (c < 15) {
            int nb = buf ^ 1;
            sA[nb][la_k + 0][la_r] = ra.x; sA[nb][la_k + 1][la_r] = ra.y;
            sA[nb][la_k + 2][la_r] = ra.z; sA[nb][la_k + 3][la_r] = ra.w;
            *(float4*)&sB[nb][lb_k][lb_j] = rb;
            __syncthreads();
        }
    }

    float4 bv0 = *(const float4*)&bias[b_off + c4];
    float4 bv1 = *(const float4*)&bias[b_off + 64 + c4];
    float bb[8] = {bv0.x, bv0.y, bv0.z, bv0.w, bv1.x, bv1.y, bv1.z, bv1.w};
    if (addv) {
        const float* av = addv + (row0 >> 10) * 128;
        float4 g0 = __ldg((const float4*)&av[c4]);
        float4 g1 = __ldg((const float4*)&av[64 + c4]);
        bb[0] += g0.x; bb[1] += g0.y; bb[2] += g0.z; bb[3] += g0.w;
        bb[4] += g1.x; bb[5] += g1.y; bb[6] += g1.z; bb[7] += g1.w;
    }
    #pragma unroll
    for (int i = 0; i < 8; i++) {
        size_t r = row0 + r4 + (i & 3) + (i >> 2) * 64;
        float4 o0, o1;
        o0.x = acc[i][0] + bb[0]; o0.y = acc[i][1] + bb[1];
        o0.z = acc[i][2] + bb[2]; o0.w = acc[i][3] + bb[3];
        o1.x = acc[i][4] + bb[4]; o1.y = acc[i][5] + bb[5];
        o1.z = acc[i][6] + bb[6]; o1.w = acc[i][7] + bb[7];
        *(float4*)&out[r * 128 + c4] = o0;
        *(float4*)&out[r * 128 + 64 + c4] = o1;
    }
}

// ---------------- small GEMM (rows <= 32*blocks), for q / final tiny --------
__global__ void k_matmul(const float* __restrict__ in, int in_ld,
                         const float* __restrict__ W, int w_ld, int w_off,
                         const float* __restrict__ bias, int b_off,
                         float* __restrict__ out, int out_ld, int rows,
                         float bscale) {
    __shared__ float sA[32][128];
    int row0 = blockIdx.x * 32;
    for (int i = threadIdx.x; i < 32 * 128; i += 256) {
        int r = i >> 7, c = i & 127;
        sA[r][c] = (row0 + r < rows) ? in[(size_t)(row0 + r) * in_ld + c] : 0.f;
    }
    __syncthreads();
    int tj = threadIdx.x & 31, tm = threadIdx.x >> 5;
    int j4 = tj * 4;
    float acc[4][4] = {};
    const float* Wp = W + w_off + j4;
    #pragma unroll 4
    for (int k0 = 0; k0 < 128; k0 += 4) {
        float4 a0 = *(const float4*)&sA[tm * 4 + 0][k0];
        float4 a1 = *(const float4*)&sA[tm * 4 + 1][k0];
        float4 a2 = *(const float4*)&sA[tm * 4 + 2][k0];
        float4 a3 = *(const float4*)&sA[tm * 4 + 3][k0];
        float av[4][4] = {{a0.x, a0.y, a0.z, a0.w},
                          {a1.x, a1.y, a1.z, a1.w},
                          {a2.x, a2.y, a2.z, a2.w},
                          {a3.x, a3.y, a3.z, a3.w}};
        #pragma unroll
        for (int kk = 0; kk < 4; kk++) {
            float4 w = __ldg((const float4*)(Wp + (size_t)(k0 + kk) * w_ld));
            #pragma unroll
            for (int m = 0; m < 4; m++) {
                acc[m][0] += av[m][kk] * w.x;
                acc[m][1] += av[m][kk] * w.y;
                acc[m][2] += av[m][kk] * w.z;
                acc[m][3] += av[m][kk] * w.w;
            }
        }
    }
    float4 bv = *(const float4*)&bias[b_off + j4];
    #pragma unroll
    for (int m = 0; m < 4; m++) {
        int r = row0 + tm * 4 + m;
        if (r < rows) {
            float4 o;
            o.x = acc[m][0] + bv.x * bscale; o.y = acc[m][1] + bv.y * bscale;
            o.z = acc[m][2] + bv.z * bscale; o.w = acc[m][3] + bv.w * bscale;
            *(float4*)&out[(size_t)r * out_ld + j4] = o;
        }
    }
}

// ---------------- attention: one block per (graph, head) -------------------
__global__ void k_attn() {
    __shared__ float s_q[8][32];
    __shared__ float s_kt[64 * 37];
    __shared__ float s_sc[8][1024];
    int b = blockIdx.x >> 2, h = blockIdx.x & 3;
    int tid = threadIdx.x;
    {
        int t = tid >> 5, d = tid & 31;
        s_q[t][d] = g_q[t * HH + h * 32 + d];
    }
    __syncthreads();
    int t = tid >> 5, g = tid & 31;
    float qr[32];
    #pragma unroll
    for (int d = 0; d < 32; d++) qr[d] = s_q[t][d];
    const float scale = 0.17677669529663689f;

    for (int kk0 = 0; kk0 < 1024; kk0 += 64) {
        __syncthreads();
        for (int i = tid; i < 64 * 32; i += 256) {
            int key = i >> 5, d = i & 31;
            s_kt[key * 37 + d] = g_k[((size_t)(b * 1024 + kk0 + key)) * HH + h * 32 + d];
        }
        __syncthreads();
        #pragma unroll
        for (int kidx = 0; kidx < 2; kidx++) {
            int key = g + kidx * 32;
            float acc = 0.f;
            #pragma unroll
            for (int d = 0; d < 32; d++) acc += s_kt[key * 37 + d] * qr[d];
            s_sc[t][kk0 + key] = acc * scale;
        }
    }
    __syncthreads();
    float m = -1e30f;
    for (int i = g; i < 1024; i += 32) m = fmaxf(m, s_sc[t][i]);
    #pragma unroll
    for (int d = 16; d; d >>= 1) m = fmaxf(m, __shfl_xor_sync(0xffffffffu, m, d));
    float sum = 0.f;
    for (int i = g; i < 1024; i += 32) {
        float e = __expf(s_sc[t][i] - m);
        s_sc[t][i] = e;
        sum += e;
    }
    #pragma unroll
    for (int d = 16; d; d >>= 1) sum += __shfl_xor_sync(0xffffffffu, sum, d);
    float inv = 1.f / sum;
    for (int i = g; i < 1024; i += 32) s_sc[t][i] *= inv;
    __syncthreads();
    float acc = 0.f;
    const float* vbase = g_v + (size_t)b * 1024 * HH + h * 32 + g;
    #pragma unroll 4
    for (int kk = 0; kk < 1024; kk++)
        acc += s_sc[t][kk] * __ldg(vbase + (size_t)kk * HH);
    g_o[((size_t)b * 8 + t) * HH + h * 32 + g] = acc;
}

// ---------------- mamba: one block per batch element, 256 threads ----------
__global__ void k_mamba(const float* __restrict__ in_w, const float* __restrict__ conv_w,
                        const float* __restrict__ conv_b, const float* __restrict__ x_w,
                        const float* __restrict__ dt_w, const float* __restrict__ dt_b,
                        const float* __restrict__ A_log, const float* __restrict__ Dp,
                        const float* __restrict__ out_w, const float* __restrict__ norm_w,
                        const float* __restrict__ normf_w) {
    __shared__ float s_res[8][128];
    __shared__ float s_h[8][128];
    __shared__ float s_u[8][256];
    __shared__ float s_ssm[8][40];
    __shared__ float s_y[8][256];
    __shared__ float s_o[8][128];
    __shared__ float s_r[8];
    int b = blockIdx.x, tid = threadIdx.x;

    for (int i = tid; i < 8 * 128; i += 256)
        s_res[i >> 7][i & 127] = g_tok[(size_t)b * 1024 + i];
    __syncthreads();
    {
        int t = tid >> 5, lane = tid & 31;
        float ss = 0.f;
        for (int c = lane; c < 128; c += 32) { float v = s_res[t][c]; ss += v * v; }
        #pragma unroll
        for (int d = 16; d; d >>= 1) ss += __shfl_xor_sync(0xffffffffu, ss, d);
        float r = rsqrtf(ss / 128.f + 1e-5f);
        for (int c = lane; c < 128; c += 32) s_h[t][c] = s_res[t][c] * r * norm_w[c];
    }
    __syncthreads();

    int i = tid;
    float u_r[8] = {}, gate_r[8] = {};
    for (int k = 0; k < 128; k++) {
        float w0 = __ldg(&in_w[k * 512 + i]);
        float w1 = __ldg(&in_w[k * 512 + 256 + i]);
        #pragma unroll
        for (int t = 0; t < 8; t++) {
            float hv = s_h[t][k];
            u_r[t] += hv * w0;
            gate_r[t] += hv * w1;
        }
    }
    float cw0 = conv_w[i * 4 + 0], cw1 = conv_w[i * 4 + 1];
    float cw2 = conv_w[i * 4 + 2], cw3 = conv_w[i * 4 + 3];
    float cb = conv_b[i];
    float uc[8];
    #pragma unroll
    for (int t = 0; t < 8; t++) {
        float c = cb + cw3 * u_r[t];
        if (t >= 1) c += cw2 * u_r[t - 1];
        if (t >= 2) c += cw1 * u_r[t - 2];
        if (t >= 3) c += cw0 * u_r[t - 3];
        uc[t] = c / (1.f + expf(-c));
        s_u[t][i] = uc[t];
    }
    __syncthreads();
    for (int idx = tid; idx < 8 * 40; idx += 256) {
        int t = idx / 40, j = idx % 40;
        float a = 0.f;
        for (int k = 0; k < 256; k++) a += s_u[t][k] * __ldg(&x_w[k * 40 + j]);
        s_ssm[t][j] = a;
    }
    __syncthreads();
    float dtv[8];
    {
        float acc[8] = {};
        for (int r = 0; r < 8; r++) {
            float w = __ldg(&dt_w[r * 256 + i]);
            #pragma unroll
            for (int t = 0; t < 8; t++) acc[t] += s_ssm[t][r] * w;
        }
        float db = dt_b[i];
        #pragma unroll
        for (int t = 0; t < 8; t++) {
            float a = acc[t] + db;
            dtv[t] = (a > 20.f) ? a : log1pf(expf(a));
        }
    }
    float Ar[16];
    #pragma unroll
    for (int s = 0; s < 16; s++) Ar[s] = -expf(A_log[i * 16 + s]);
    float Dv = Dp[i];
    float hst[16] = {};
    #pragma unroll
    for (int t = 0; t < 8; t++) {
        float dtt = dtv[t], ut = uc[t];
        float y = 0.f;
        #pragma unroll
        for (int s = 0; s < 16; s++) {
            float dA = expf(dtt * Ar[s]);
            hst[s] = dA * hst[s] + dtt * s_ssm[t][8 + s] * ut;
            y += hst[s] * s_ssm[t][24 + s];
        }
        y += ut * Dv;
        float gt = gate_r[t];
        y *= gt / (1.f + expf(-gt));
        s_y[t][i] = y;
    }
    __syncthreads();
    for (int idx = tid; idx < 8 * 128; idx += 256) {
        int t = idx >> 7, j = idx & 127;
        float a = 0.f;
        for (int k = 0; k < 256; k++) a += s_y[t][k] * __ldg(&out_w[k * 128 + j]);
        s_o[t][j] = s_res[t][j] + a;
    }
    __syncthreads();
    {
        int t = tid >> 5, lane = tid & 31;
        float ss = 0.f;
        for (int c = lane; c < 128; c += 32) { float v = s_o[t][c]; ss += v * v; }
        #pragma unroll
        for (int d = 16; d; d >>= 1) ss += __shfl_xor_sync(0xffffffffu, ss, d);
        if (lane == 0) s_r[t] = rsqrtf(ss / 128.f + 1e-5f);
    }
    __syncthreads();
    if (tid < 128) {
        float a = 0.f;
        #pragma unroll
        for (int t = 0; t < 8; t++) a += s_o[t][tid] * s_r[t];
        g_gf[b * 128 + tid] = a * normf_w[tid] * 0.125f;
    }
}

// ---------------- per-graph sum of agg: gs[b] = sum_n agg[b*1024+n] --------
__global__ void k_graphsum() {
    __shared__ float s[512];
    int b = blockIdx.x, tid = threadIdx.x;
    int j = tid & 127, q = tid >> 7;
    const float* p = g_agg + ((size_t)(b * 1024 + q * 256)) * 128 + j;
    float a = 0.f;
    #pragma unroll 4
    for (int n = 0; n < 256; n++) a += p[(size_t)n * 128];
    s[tid] = a;
    __syncthreads();
    if (tid < 128)
        g_gs[b * 128 + tid] = s[tid] + s[tid + 128] + s[tid + 256] + s[tid + 384];
}

// ---------------- host launch ----------------------------------------------
extern "C" void kernel_launch(void* const* d_in, const int* in_sizes, int n_in,
                              void* d_out, int out_size) {
    int off = (n_in >= 27) ? 0 : -2;
    auto P = [&](int i) -> const void* { return (i < 3) ? d_in[i] : d_in[i + off]; };

    const float* x_in   = (const float*)P(0);
    const int*   ei     = (const int*)P(1);
    const float* w_in   = (const float*)P(5);
    const float* b_in   = (const float*)P(6);
    const float* gin_w  = (const float*)P(7);
    const float* gin_b  = (const float*)P(8);
    const float* vt     = (const float*)P(9);
    const float* qkv_w  = (const float*)P(10);
    const float* qkv_b  = (const float*)P(11);
    const float* ao_w   = (const float*)P(12);
    const float* ao_b   = (const float*)P(13);
    const float* m_in_w   = (const float*)P(14);
    const float* m_conv_w = (const float*)P(15);
    const float* m_conv_b = (const float*)P(16);
    const float* m_x_w    = (const float*)P(17);
    const float* m_dt_w   = (const float*)P(18);
    const float* m_dt_b   = (const float*)P(19);
    const float* m_A_log  = (const float*)P(20);
    const float* m_D      = (const float*)P(21);
    const float* m_out_w  = (const float*)P(22);
    const float* m_norm_w = (const float*)P(23);
    const float* m_normf_w= (const float*)P(24);
    const float* w_out  = (const float*)P(25);
    const float* b_out  = (const float*)P(26);

    float *p_x, *p_agg, *p_k, *p_v, *p_q, *p_o, *p_tok, *p_gf, *p_gs;
    cudaGetSymbolAddress((void**)&p_x, g_x);
    cudaGetSymbolAddress((void**)&p_agg, g_agg);
    cudaGetSymbolAddress((void**)&p_k, g_k);
    cudaGetSymbolAddress((void**)&p_v, g_v);
    cudaGetSymbolAddress((void**)&p_q, g_q);
    cudaGetSymbolAddress((void**)&p_o, g_o);
    cudaGetSymbolAddress((void**)&p_tok, g_tok);
    cudaGetSymbolAddress((void**)&p_gf, g_gf);
    cudaGetSymbolAddress((void**)&p_gs, g_gs);

    // --- CSR build ---
    k_zero_dc<<<(NN + 255) / 256, 256>>>();
    k_degree<<<(EE + 255) / 256, 256>>>(ei);
    k_scan1<<<NN / 1024, 1024>>>();
    k_scan2<<<1, 32>>>();
    k_scan3<<<(NN + 255) / 256, 256>>>();
    k_scatter<<<(EE + 255) / 256, 256>>>(ei);

    // --- GIN input layer: x = gin(x_in, w_in, b_in) ---
    k_aggregate<<<NN / 8, 256>>>(x_in);
    k_gemm128<<<NN / 128, 256>>>(p_agg, w_in, HH, 0, b_in, 0, p_x, nullptr);

    // --- two (GIN + attn-pool + mamba) blocks ---
    for (int l = 0; l < 2; l++) {
        // aggregation for g (from current x)
        k_aggregate<<<NN / 8, 256>>>(p_x);
        // K, V projections from x
        k_gemm128<<<NN / 128, 256>>>(p_x, qkv_w + (size_t)l * HH * 3 * HH, 3 * HH, HH,
                                     qkv_b + l * 3 * HH, HH, p_k, nullptr);
        k_gemm128<<<NN / 128, 256>>>(p_x, qkv_w + (size_t)l * HH * 3 * HH, 3 * HH, 2 * HH,
                                     qkv_b + l * 3 * HH, 2 * HH, p_v, nullptr);
        // q = vt @ Wq + bq (8 rows)
        k_matmul<<<1, 256>>>(vt + l * TT * HH, HH, qkv_w + (size_t)l * HH * 3 * HH, 3 * HH, 0,
                             qkv_b + l * 3 * HH, 0, p_q, HH, TT, 1.f);
        // attention pool
        k_attn<<<BB * 4, 256>>>();
        // tokens = o @ ao_w + ao_b (1024 rows)
        k_gemm128<<<(BB * TT) / 128, 256>>>(p_o, ao_w + (size_t)l * HH * HH, HH, 0,
                                            ao_b + l * HH, 0, p_tok, nullptr);
        // mamba -> g_gf
        k_mamba<<<BB, 256>>>(m_in_w, m_conv_w, m_conv_b, m_x_w, m_dt_w, m_dt_b,
                             m_A_log, m_D, m_out_w, m_norm_w, m_normf_w);
        // x = gin(x) + gf[batch]  (fused epilogue, writes x in place; A = agg)
        k_gemm128<<<NN / 128, 256>>>(p_agg, gin_w + (size_t)l * HH * HH, HH, 0,
                                     gin_b + l * HH, 0, p_x, p_gf);
    }

    // --- output: segment_sum(gin(x)) = (sum_graph agg) @ w_out + 1024*b_out ---
    k_aggregate<<<NN / 8, 256>>>(p_x);
    k_graphsum<<<BB, 512>>>();
    k_matmul<<<BB / 32, 256>>>(p_gs, HH, w_out, HH, 0, b_out, 0,
                               (float*)d_out, HH, BB, 1024.f);
}